// round 8
// baseline (speedup 1.0000x reference)
#include <cuda_runtime.h>
#include <math.h>

// Problem constants
#define BB 64
#define TT 1024
#define DD 512
#define UU 1024
#define GG 4096           // 4*U
#define MM 65536          // B*T
#define NCTA 128          // persistent recurrent grid

// ---------------- scratch (static __device__, no allocs) ----------------
__device__ float g_xproj[(size_t)MM * GG];        // 1 GiB: x@Wx + bias, layout [t][b][g]
__device__ float g_hT[2][UU * BB];                // double-buffered hidden state, TRANSPOSED [u][b]
__device__ unsigned g_count;
__device__ unsigned g_release;

// phase-2 dynamic smem: Wh slice [1024][8 units][4 gates] + double-buffered h chunks
#define WT_ELEMS (1024 * 32)
#define HS_ELEMS (2 * 16 * 64)
#define SMEM_RECUR ((WT_ELEMS + HS_ELEMS) * 4)

// ---------------- packed f32x2 FMA (Blackwell FFMA2, PTX-only) ----------------
__device__ __forceinline__ float2 ffma2(float2 a, float2 b, float2 c) {
    union U { float2 f; unsigned long long u; };
    U x, y, z, r;
    x.f = a; y.f = b; z.f = c;
    asm("fma.rn.f32x2 %0, %1, %2, %3;" : "=l"(r.u) : "l"(x.u), "l"(y.u), "l"(z.u));
    return r.f;
}

__device__ __forceinline__ float sigm(float x) { return 1.0f / (1.0f + expf(-x)); }

// ---------------- grid barrier (monotonic release, L2-coherent) ----------------
__device__ __forceinline__ void gridbar(unsigned s) {
    __syncthreads();
    if (threadIdx.x == 0) {
        __threadfence();
        unsigned prev = atomicAdd(&g_count, 1u);
        if (prev + 1u == (unsigned)NCTA * s) {
            atomicExch(&g_release, s);
        } else {
            volatile unsigned* rel = &g_release;
            while (*rel < s) { }
            __threadfence();
        }
    }
    __syncthreads();
}

// ---------------- init: zero h buffers + barrier state (runs every replay) ----------------
__global__ void k_init() {
    int i = blockIdx.x * blockDim.x + threadIdx.x;
    if (i < 2 * UU * BB) ((float*)g_hT)[i] = 0.0f;
    if (i == 0) { g_count = 0u; g_release = 0u; }
}

// ---------------- phase 1: x_proj = inputs(65536x512) @ Wx(512x4096) + bias ----------------
// 128(m) x 64(n) tile, 256 threads, 8x4 microtile, f32x2 paired over m.
// Output written in recurrence-friendly layout [t][b][g].
__global__ __launch_bounds__(256) void k_xproj(const float* __restrict__ A,
                                               const float* __restrict__ W,
                                               const float* __restrict__ bias) {
    __shared__ float As[16][128];   // k-major
    __shared__ float Ws[16][64];    // n-major
    const int tid = threadIdx.x;
    const int m0 = blockIdx.y * 128;
    const int n0 = blockIdx.x * 64;
    const int ry8 = (tid >> 4) * 8;
    const int cx4 = (tid & 15) * 4;

    float2 acc[4][4];
#pragma unroll
    for (int i = 0; i < 4; i++)
#pragma unroll
        for (int j = 0; j < 4; j++) acc[i][j] = make_float2(0.f, 0.f);

#pragma unroll 1
    for (int kt = 0; kt < DD; kt += 16) {
#pragma unroll
        for (int i = 0; i < 2; i++) {
            int id = tid + i * 256;
            int r = id >> 2;
            int k4 = (id & 3) << 2;
            float4 v = *reinterpret_cast<const float4*>(A + (size_t)(m0 + r) * DD + kt + k4);
            As[k4 + 0][r] = v.x; As[k4 + 1][r] = v.y;
            As[k4 + 2][r] = v.z; As[k4 + 3][r] = v.w;
        }
        {
            int kr = tid >> 4;
            int nc = (tid & 15) << 2;
            *reinterpret_cast<float4*>(&Ws[kr][nc]) =
                *reinterpret_cast<const float4*>(W + (size_t)(kt + kr) * GG + n0 + nc);
        }
        __syncthreads();
#pragma unroll
        for (int kk = 0; kk < 16; kk++) {
            float4 a0 = *reinterpret_cast<const float4*>(&As[kk][ry8]);
            float4 a1 = *reinterpret_cast<const float4*>(&As[kk][ry8 + 4]);
            float4 bv = *reinterpret_cast<const float4*>(&Ws[kk][cx4]);
            float2 A2[4] = {{a0.x, a0.y}, {a0.z, a0.w}, {a1.x, a1.y}, {a1.z, a1.w}};
            float bb4[4] = {bv.x, bv.y, bv.z, bv.w};
#pragma unroll
            for (int mi = 0; mi < 4; mi++)
#pragma unroll
                for (int nj = 0; nj < 4; nj++)
                    acc[mi][nj] = ffma2(A2[mi], make_float2(bb4[nj], bb4[nj]), acc[mi][nj]);
        }
        __syncthreads();
    }

    float b4[4];
#pragma unroll
    for (int j = 0; j < 4; j++) b4[j] = bias[n0 + cx4 + j];
#pragma unroll
    for (int mi = 0; mi < 4; mi++) {
#pragma unroll
        for (int e = 0; e < 2; e++) {
            int m = m0 + ry8 + mi * 2 + e;
            int b = m >> 10;          // batch
            int t = m & 1023;         // time
            float4 o;
            o.x = (e ? acc[mi][0].y : acc[mi][0].x) + b4[0];
            o.y = (e ? acc[mi][1].y : acc[mi][1].x) + b4[1];
            o.z = (e ? acc[mi][2].y : acc[mi][2].x) + b4[2];
            o.w = (e ? acc[mi][3].y : acc[mi][3].x) + b4[3];
            *reinterpret_cast<float4*>(g_xproj + ((size_t)t * BB + b) * GG + n0 + cx4) = o;
        }
    }
}

// ---------------- phase 2: persistent recurrence, 128 CTAs x 256 threads ----------------
// CTA owns 8 units (32 gate-columns), full k=1024. Wh slice lives in SMEM.
// Thread microtile: 2 batch rows x 1 unit x 4 gates -> cell update fully in registers.
// ONE grid barrier per step.
__global__ __launch_bounds__(256) void k_recur(const float* __restrict__ W,
                                               float* __restrict__ out) {
    extern __shared__ float smem[];
    float* wt = smem;                 // [1024][8 uoff][4 gate]
    float* hs = smem + WT_ELEMS;      // [2][16][64]

    const int tid = threadIdx.x;
    const int cta = blockIdx.x;
    const int uoff = tid & 7;
    const int bpair = tid >> 3;       // 0..31
    const int r0 = bpair * 2;         // batch rows r0, r0+1
    const int u = cta * 8 + uoff;
    const float* Wh = W + (size_t)DD * GG;   // recurrent weights = kernel rows [512,1536)

    // ---- load this CTA's Wh slice into smem (once) ----
    // i enumerates (k, gate, uoff) so 8 consecutive threads hit 8 consecutive floats.
    for (int i = tid; i < WT_ELEMS; i += 256) {
        int uo = i & 7;
        int gate = (i >> 3) & 3;
        int k = i >> 5;
        wt[k * 32 + uo * 4 + gate] =
            Wh[(size_t)k * GG + gate * UU + cta * 8 + uo];
    }
    const float* wtp = wt + uoff * 4;

    float2 c = make_float2(0.f, 0.f);

    for (int step = 0; step < TT; ++step) {
        const int p = step & 1;
        const float* hin = g_hT[p];

        // ---- prefetch this step's xproj gate values (DRAM, hidden under GEMM) ----
        float xp[2][4];
        {
            const float* xrow = g_xproj + (size_t)step * (BB * GG);
#pragma unroll
            for (int e = 0; e < 2; e++)
#pragma unroll
                for (int g = 0; g < 4; g++)
                    xp[e][g] = __ldcg(xrow + (size_t)(r0 + e) * GG + g * UU + u);
        }

        float2 acc[4];
#pragma unroll
        for (int g = 0; g < 4; g++) acc[g] = make_float2(0.f, 0.f);

        // ---- stage chunk 0 of h^T (16 k-rows x 64 b, contiguous 4KB) ----
        {
            int kk = tid >> 4;
            int b4 = (tid & 15) << 2;
            float4 v = __ldcg(reinterpret_cast<const float4*>(hin + kk * 64 + b4));
            *reinterpret_cast<float4*>(hs + kk * 64 + b4) = v;
        }

        int cur = 0;
#pragma unroll 1
        for (int ch = 0; ch < 64; ch++) {
            __syncthreads();
            if (ch < 63) {
                int kk = tid >> 4;
                int b4 = (tid & 15) << 2;
                float4 v = __ldcg(reinterpret_cast<const float4*>(
                    hin + (ch + 1) * 1024 + kk * 64 + b4));
                *reinterpret_cast<float4*>(hs + (cur ^ 1) * 1024 + kk * 64 + b4) = v;
            }
            const float* hsb = hs + cur * 1024;
            const float* wchunk = wtp + ch * 16 * 32;
#pragma unroll
            for (int kk = 0; kk < 16; kk++) {
                float2 h2 = *reinterpret_cast<const float2*>(hsb + kk * 64 + r0);
                float4 w4 = *reinterpret_cast<const float4*>(wchunk + kk * 32);
                acc[0] = ffma2(h2, make_float2(w4.x, w4.x), acc[0]);
                acc[1] = ffma2(h2, make_float2(w4.y, w4.y), acc[1]);
                acc[2] = ffma2(h2, make_float2(w4.z, w4.z), acc[2]);
                acc[3] = ffma2(h2, make_float2(w4.w, w4.w), acc[3]);
            }
            cur ^= 1;
        }

        // ---- cell update, fully register-local ----
        float2 hv;
        {
            float i0 = acc[0].x + xp[0][0], i1 = acc[0].y + xp[1][0];
            float j0 = acc[1].x + xp[0][1], j1 = acc[1].y + xp[1][1];
            float f0 = acc[2].x + xp[0][2], f1 = acc[2].y + xp[1][2];
            float o0 = acc[3].x + xp[0][3], o1 = acc[3].y + xp[1][3];
            c.x = c.x * sigm(f0 + 1.0f) + sigm(i0) * tanhf(j0);
            c.y = c.y * sigm(f1 + 1.0f) + sigm(i1) * tanhf(j1);
            hv.x = tanhf(c.x) * sigm(o0);
            hv.y = tanhf(c.y) * sigm(o1);
        }

        // h^T write (coalesced float2), output write [b][t][u]
        __stcg(reinterpret_cast<float2*>(g_hT[p ^ 1] + u * 64 + r0), hv);
        out[(size_t)(r0)     * (TT * UU) + (size_t)step * UU + u] = hv.x;
        out[(size_t)(r0 + 1) * (TT * UU) + (size_t)step * UU + u] = hv.y;

        gridbar(step + 1);
    }
}

// ---------------- launch ----------------
extern "C" void kernel_launch(void* const* d_in, const int* in_sizes, int n_in,
                              void* d_out, int out_size) {
    (void)in_sizes; (void)n_in; (void)out_size;
    const float* inputs = (const float*)d_in[0];
    const float* kern   = (const float*)d_in[1];
    const float* bias   = (const float*)d_in[2];
    float* out = (float*)d_out;

    static bool attr_done = false;
    if (!attr_done) {
        cudaFuncSetAttribute(k_recur, cudaFuncAttributeMaxDynamicSharedMemorySize,
                             SMEM_RECUR);
        attr_done = true;
    }

    k_init<<<512, 256>>>();
    dim3 g1(GG / 64, MM / 128);   // (64, 512)
    k_xproj<<<g1, 256>>>(inputs, kern, bias);
    k_recur<<<NCTA, 256, SMEM_RECUR>>>(kern, out);
}